// round 10
// baseline (speedup 1.0000x reference)
#include <cuda_runtime.h>
#include <cuda_bf16.h>
#include <cstdint>

#define DEPTH_DIM 256
#define CAP       16             // slots per pixel; P(Poisson(1.11) >= 16) ~ 1e-13
#define MAX_PIX   (1 << 19)      // up to 512K pixels

__device__ int   g_cnt[MAX_PIX];              // zero-init at load; self-reset each launch
__device__ uint4 g_bin[MAX_PIX * CAP];        // {pd, na2, W=2^(2048 na2), U=2^(-64 na2)}

__device__ __forceinline__ float ex2_fast(float x) {
    float y;
    asm("ex2.approx.ftz.f32 %0, %1;" : "=f"(y) : "f"(x));
    return y;
}

// ---------------------------------------------------------------------------
// K1: bin points by pixel. Precompute na2 = C / sigma^2 (C = -0.5*h^2*log2 e,
//     h = 6/255) plus the recurrence constants W = 2^(2048*na2) and
//     U = 2^(-64*na2), so the fused hot loop needs no division and only
//     3 MUFUs per point-lane (inits) instead of 8.
// ---------------------------------------------------------------------------
__global__ void bin_kernel(const int2* __restrict__ pos,
                           const int*  __restrict__ depth,
                           const float* __restrict__ conf,
                           const int*  __restrict__ pW, int npts) {
    int i = blockIdx.x * blockDim.x + threadIdx.x;
    if (i >= npts) return;
    int W = __ldg(pW);
    int2 uv = __ldg(&pos[i]);
    int lin = uv.y * W + uv.x;
    int slot = atomicAdd(&g_cnt[lin], 1);
    if (slot < CAP) {
        const float C = -0.5f * (6.0f / 255.0f) * (6.0f / 255.0f) * 1.4426950408889634f;
        float sigma = __ldg(&conf[i]);
        float na2 = C / (sigma * sigma);
        uint4 v;
        v.x = (unsigned)__ldg(&depth[i]);
        v.y = __float_as_uint(na2);
        v.z = __float_as_uint(ex2_fast(2048.0f * na2));
        v.w = __float_as_uint(ex2_fast(-64.0f * na2));
        g_bin[lin * CAP + slot] = v;
    }
}

// ---------------------------------------------------------------------------
// K2: fused accumulate + transposed write (R6 skeleton; recurrence hot loop).
//   Block = 32 consecutive pixels -> contiguous 8KB slab region, staged with
//   one coalesced burst (256 thr x 2x16B); counters staged + reset.
//   Warp w owns pixels 4w..4w+3; lane L owns depths d = L + 32m.
//   Math: j_m = (L - pd) + 32m;  e_m = 2^(na2 j_m^2) via e*=v, v*=W;
//   window value g_m = e_m            for d <= pd   (k = j_m)
//                g_m = e_m * c_m      for d >  pd   (k = j_m - 1),
//   c_m = 2^(na2 (1 - 2 j_m)) via c*=U.  Dup k=0 at d=pd,pd+1 matches ref.
//   Tile stride 33 keeps column store and row read conflict-free.
// ---------------------------------------------------------------------------
__global__ void fused_kernel(float* __restrict__ out, int HW) {
    __shared__ float tile[DEPTH_DIM][33];
    __shared__ uint4 spts[32][CAP];            // 8KB
    __shared__ int   scnt[32];

    int tid  = threadIdx.x;
    int lane = tid & 31;
    int w    = tid >> 5;
    int pBase = blockIdx.x * 32;

    // stage counters (and reset them for the next graph replay)
    if (tid < 32) {
        int p = pBase + tid;
        int c = 0;
        if (p < HW) {
            c = min(g_cnt[p], CAP);
            g_cnt[p] = 0;
        }
        scnt[tid] = c;
    }
    // stage the block's contiguous 8KB slab region: 256 threads x 2 x 16B
    {
        const uint4* src = reinterpret_cast<const uint4*>(g_bin + (size_t)pBase * CAP);
        uint4* dst = &spts[0][0];
        dst[tid]       = src[tid];
        dst[tid + 256] = src[tid + 256];       // 32*CAP = 512 uint4s total
    }
    __syncthreads();

    #pragma unroll
    for (int jj = 0; jj < 4; ++jj) {
        int pl = w * 4 + jj;                   // pixel-in-block 0..31
        int cnt = scnt[pl];
        float acc[8] = {0.f, 0.f, 0.f, 0.f, 0.f, 0.f, 0.f, 0.f};
        for (int t = 0; t < cnt; ++t) {
            uint4 pv = spts[pl][t];            // smem broadcast (16B)
            int   pd  = (int)pv.x;
            float na2 = __uint_as_float(pv.y);
            float Wc  = __uint_as_float(pv.z);
            float Uc  = __uint_as_float(pv.w);

            int   k0  = lane - pd;             // j for m=0
            float j0  = (float)k0;
            float e  = ex2_fast(na2 * j0 * j0);
            float vr = ex2_fast(na2 * fmaf(64.0f, j0, 1024.0f));
            float c  = ex2_fast(na2 * fmaf(-2.0f, j0, 1.0f));

            float g[8];
            float s = 0.0f;
            #pragma unroll
            for (int m = 0; m < 8; ++m) {
                float gm = (k0 + 32 * m > 0) ? e * c : e;   // d > pd ?
                g[m] = gm;
                s = fmaf(gm, gm, s);
                e *= vr;  vr *= Wc;  c *= Uc;
            }
            #pragma unroll
            for (int o = 16; o > 0; o >>= 1)
                s += __shfl_xor_sync(0xffffffffu, s, o);
            float inv = rsqrtf(s);             // s >= 1 (k=0 term), no eps clamp
            #pragma unroll
            for (int m = 0; m < 8; ++m)
                acc[m] = fmaf(g[m], inv, acc[m]);
        }
        // column pl: bank = (lane + pl) % 32 -> conflict-free
        #pragma unroll
        for (int m = 0; m < 8; ++m)
            tile[lane + 32 * m][pl] = acc[m];
    }
    __syncthreads();

    // coalesced output: each warp writes 32 consecutive pixels per depth row
    int p = pBase + lane;
    if (p < HW) {
        #pragma unroll
        for (int m = 0; m < 32; ++m) {
            int d = w + m * 8;
            out[(size_t)d * HW + p] = tile[d][lane];
        }
    }
}

// ---------------------------------------------------------------------------
// Launch
// ---------------------------------------------------------------------------
extern "C" void kernel_launch(void* const* d_in, const int* in_sizes, int n_in,
                              void* d_out, int out_size) {
    const int2*  pos   = (const int2*)d_in[0];   // [N,2] int32 (u=x, v=y)
    const int*   depth = (const int*)d_in[1];    // [N,1] int32
    const float* conf  = (const float*)d_in[2];  // [N,1] float32
    const int*   pW    = (const int*)d_in[4];    // feat_w scalar

    int npts = in_sizes[1];
    int HW   = out_size / DEPTH_DIM;

    bin_kernel<<<(npts + 255) / 256, 256>>>(pos, depth, conf, pW, npts);
    fused_kernel<<<(HW + 31) / 32, 256>>>((float*)d_out, HW);
}